// round 14
// baseline (speedup 1.0000x reference)
#include <cuda_runtime.h>
#include <cuda_bf16.h>

// Fixed shapes from setup_inputs
#define BB 8
#define KK 8
#define KH 2                  // channels per block (K split across 4 blocks)
#define NKQ 4                 // K quarters
#define HH 1024
#define WW 1024
#define CH 16                 // rows per block chunk (halo overhead 1/16)
#define NBY (HH / CH)         // 64 blocks along H
#define NBLOCKS (NBY * BB * NKQ)  // 2048 total
#define GAMMA_C 10.0f
#define EPS_SQRT_C 1e-24f

typedef unsigned long long u64;

// ---- Blackwell packed f32x2 helpers ----
__device__ __forceinline__ u64 pk2(float lo, float hi) {
    u64 r; asm("mov.b64 %0, {%1, %2};" : "=l"(r) : "f"(lo), "f"(hi)); return r;
}
__device__ __forceinline__ void upk2(u64 v, float& lo, float& hi) {
    asm("mov.b64 {%0, %1}, %2;" : "=f"(lo), "=f"(hi) : "l"(v));
}
__device__ __forceinline__ u64 add2(u64 a, u64 b) {
    u64 d; asm("add.rn.f32x2 %0, %1, %2;" : "=l"(d) : "l"(a), "l"(b)); return d;
}
__device__ __forceinline__ u64 mul2(u64 a, u64 b) {
    u64 d; asm("mul.rn.f32x2 %0, %1, %2;" : "=l"(d) : "l"(a), "l"(b)); return d;
}
__device__ __forceinline__ u64 fma2(u64 a, u64 b, u64 c) {
    u64 d; asm("fma.rn.f32x2 %0, %1, %2, %3;" : "=l"(d) : "l"(a), "l"(b), "l"(c)); return d;
}

// Per-block partials: [y][b*16 + quarter*4 + q]; q<2: nom[kk=q], q>=2: den[kk=q-2]
__device__ float g_part[NBY * BB * 16];
__device__ unsigned int g_count = 0;   // zero-init; last block resets it

__global__ __launch_bounds__(256, 4) void clustering_fused_kernel(
    const float* __restrict__ img,      // (B,1,H,W)
    const float* __restrict__ spacing,  // (2,)
    const float* __restrict__ p,        // (B,K,H,W)
    float* __restrict__ out)
{
    const int b    = blockIdx.z;
    const int quar = blockIdx.x;             // which K quarter (0..3)
    const int h0   = blockIdx.y * CH;
    const int w0   = 4 * threadIdx.x;        // 256 threads cover W=1024 via float4
    const int idxR = (w0 + 4 < WW) ? (w0 + 4) : (WW - 1);  // clamped right col

    const float sx = spacing[0];
    const float sy = spacing[1];
    const float smin   = fminf(sx, sy);
    const float gsmin  = GAMMA_C * smin;
    const float inv_sx = 1.0f / sx;
    const float inv_sy = 1.0f / sy;

    const u64 ISX2 = pk2(inv_sx, inv_sx);
    const u64 ISY2 = pk2(inv_sy, inv_sy);
    const u64 NEG1 = pk2(-1.0f, -1.0f);
    const u64 NEG2 = pk2(-2.0f, -2.0f);

    const float* __restrict__ Ib = img + (size_t)b * HH * WW;
    const float* __restrict__ pb = p + (size_t)b * KK * HH * WW
                                     + (size_t)quar * KH * HH * WW;

    u64 nom2[KH], den2[KH];
    const u64 Z = pk2(0.0f, 0.0f);
#pragma unroll
    for (int k = 0; k < KH; k++) { nom2[k] = Z; den2[k] = Z; }

    // Prime current row registers (row h0)
    float4 iC = *(const float4*)(Ib + (size_t)h0 * WW + w0);
    float4 pC[KH];
#pragma unroll
    for (int k = 0; k < KH; k++)
        pC[k] = *(const float4*)(pb + (size_t)k * HH * WW + (size_t)h0 * WW + w0);

    for (int r = 0; r < CH; r++) {
        const int h  = h0 + r;
        const int hp = (h + 1 < HH) ? (h + 1) : (HH - 1);
        const size_t offC = (size_t)h  * WW;
        const size_t offN = (size_t)hp * WW;

        // ---- one batch of 6 independent loads ----
        float4 iN = *(const float4*)(Ib + offN + w0);
        float  iR = Ib[offC + idxR];
        float4 pN[KH];
        float  pR[KH];
#pragma unroll
        for (int k = 0; k < KH; k++) {
            const float* __restrict__ pk_ = pb + (size_t)k * HH * WW;
            pN[k] = *(const float4*)(pk_ + offN + w0);
            pR[k] = pk_[offC + idxR];
        }

        // ---- edge weights (packed gradient math, scalar MUFU tail) ----
        u64 wE01, wE23, tE01, tE23;
        {
            const u64 ic01 = pk2(iC.x, iC.y), ic23 = pk2(iC.z, iC.w);
            const u64 in01 = pk2(iN.x, iN.y), in23 = pk2(iN.z, iN.w);
            const u64 ir01 = pk2(iC.y, iC.z), ir23 = pk2(iC.w, iR);

            const u64 ix01 = fma2(ic01, NEG1, in01);   // iN - iC
            const u64 ix23 = fma2(ic23, NEG1, in23);
            const u64 iy01 = fma2(ic01, NEG1, ir01);   // right - center
            const u64 iy23 = fma2(ic23, NEG1, ir23);

            const u64 gx01 = mul2(ix01, ISX2), gx23 = mul2(ix23, ISX2);
            const u64 gy01 = mul2(iy01, ISY2), gy23 = mul2(iy23, ISY2);
            const u64 gn01 = fma2(gy01, gy01, mul2(gx01, gx01));
            const u64 gn23 = fma2(gy23, gy23, mul2(gx23, gx23));

            float g0, g1, g2, g3;
            upk2(gn01, g0, g1); upk2(gn23, g2, g3);
            const float w0_ = 1.0f / fmaf(gsmin, sqrtf(fmaxf(g0, EPS_SQRT_C)), 1.0f);
            const float w1_ = 1.0f / fmaf(gsmin, sqrtf(fmaxf(g1, EPS_SQRT_C)), 1.0f);
            const float w2_ = 1.0f / fmaf(gsmin, sqrtf(fmaxf(g2, EPS_SQRT_C)), 1.0f);
            const float w3_ = 1.0f / fmaf(gsmin, sqrtf(fmaxf(g3, EPS_SQRT_C)), 1.0f);
            wE01 = pk2(w0_, w1_); wE23 = pk2(w2_, w3_);
            tE01 = pk2(fmaf(2.0f, w0_, 1.0f), fmaf(2.0f, w1_, 1.0f));
            tE23 = pk2(fmaf(2.0f, w2_, 1.0f), fmaf(2.0f, w3_, 1.0f));
        }

#pragma unroll
        for (int k = 0; k < KH; k++) {
            const u64 pc01 = pk2(pC[k].x, pC[k].y), pc23 = pk2(pC[k].z, pC[k].w);
            const u64 pr01 = pk2(pC[k].y, pC[k].z), pr23 = pk2(pC[k].w, pR[k]);
            const u64 pn01 = pk2(pN[k].x, pN[k].y), pn23 = pk2(pN[k].z, pN[k].w);

            // dif = (pn + pr) - 2*pc ; nom += pc*(pc + wE*dif) ; den += pc*(1+2wE)
            const u64 s01 = add2(pn01, pr01), s23 = add2(pn23, pr23);
            const u64 d01 = fma2(NEG2, pc01, s01), d23 = fma2(NEG2, pc23, s23);
            const u64 t01 = fma2(wE01, d01, pc01), t23 = fma2(wE23, d23, pc23);
            nom2[k] = fma2(pc01, t01, nom2[k]);
            nom2[k] = fma2(pc23, t23, nom2[k]);
            den2[k] = fma2(pc01, tE01, den2[k]);
            den2[k] = fma2(pc23, tE23, den2[k]);

            pC[k] = pN[k];   // roll row registers
        }
        iC = iN;
    }

    // ---- horizontal add of packed accumulators ----
    float nom[KH], den[KH];
#pragma unroll
    for (int k = 0; k < KH; k++) {
        float a, b2;
        upk2(nom2[k], a, b2); nom[k] = a + b2;
        upk2(den2[k], a, b2); den[k] = a + b2;
    }

    // ---- Block reduction of the 4 quantities ----
    __shared__ float sred[8][4];
    const int lane = threadIdx.x & 31;
    const int warp = threadIdx.x >> 5;

#pragma unroll
    for (int q = 0; q < 4; q++) {
        float v = (q < KH) ? nom[q] : den[q - KH];
#pragma unroll
        for (int off = 16; off > 0; off >>= 1)
            v += __shfl_xor_sync(0xFFFFFFFFu, v, off);
        if (lane == 0) sred[warp][q] = v;
    }
    __syncthreads();

    if (threadIdx.x < 4) {
        const int q = threadIdx.x;
        float v = 0.0f;
#pragma unroll
        for (int wp = 0; wp < 8; wp++) v += sred[wp][q];
        g_part[(size_t)blockIdx.y * (BB * 16) + b * 16 + quar * 4 + q] = v;
    }

    // ---- Last-block finalize (ticket pattern; counter self-resets) ----
    __shared__ bool s_last;
    __threadfence();
    __syncthreads();
    if (threadIdx.x == 0) {
        unsigned int ticket = atomicAdd(&g_count, 1u);
        s_last = (ticket == NBLOCKS - 1);
    }
    __syncthreads();

    if (s_last) {
        __shared__ float s[256];
        __shared__ float c[BB * KK];
        const int t = threadIdx.x;
        const int q  = t & 127;
        const int hy = t >> 7;

        float v = 0.0f;
#pragma unroll 8
        for (int y = hy * (NBY / 2); y < (hy + 1) * (NBY / 2); y++)
            v += g_part[(size_t)y * (BB * 16) + q];
        s[t] = v;
        __syncthreads();

        if (t < BB * KK) {
            const int bb = t >> 3, k = t & 7;
            const int qr = k >> 1, kk = k & 1;
            const int cn = bb * 16 + qr * 4 + kk;       // nom combo
            const int cd = cn + 2;                      // den combo
            const float tn = s[cn] + s[128 + cn];
            const float td = s[cd] + s[128 + cd];
            c[t] = tn / td;                // cut_cost[b,k]
        }
        __syncthreads();

        if (t == 0) {
            float sum = 0.0f;
            for (int j = 0; j < BB * KK; j++) sum += c[j];
            out[0] = (float)(BB * KK) - sum;
            g_count = 0;                   // reset for next graph replay
        }
    }
}

extern "C" void kernel_launch(void* const* d_in, const int* in_sizes, int n_in,
                              void* d_out, int out_size) {
    const float* img     = (const float*)d_in[0];  // (8,1,1024,1024)
    const float* spacing = (const float*)d_in[1];  // (2,)
    const float* p       = (const float*)d_in[2];  // (8,8,1024,1024)
    float* out = (float*)d_out;

    dim3 grid(NKQ, NBY, BB);   // (4, 64, 8) = 2048 blocks
    clustering_fused_kernel<<<grid, 256>>>(img, spacing, p, out);
}

// round 15
// speedup vs baseline: 1.0797x; 1.0797x over previous
#include <cuda_runtime.h>
#include <cuda_bf16.h>
#include <cstdint>

// Fixed shapes from setup_inputs
#define BB 8
#define KK 8
#define KH 4                  // channels per block (K split across 2 blocks)
#define HH 1024
#define WW 1024
#define CH 8                  // rows computed per block
#define NBY (HH / CH)         // 128
#define NBLOCKS (NBY * BB * 2)  // 2048
#define GAMMA_C 10.0f
#define EPS_SQRT_C 1e-24f

#define NSTG 3
#define SETF (5 * WW)                      // floats per row-set: I + 4 p rows
#define SET_BYTES (SETF * 4)               // 20480
#define DYN_SMEM (NSTG * SET_BYTES)        // 61440

typedef unsigned long long u64;

// ---- packed f32x2 helpers ----
__device__ __forceinline__ u64 pk2(float lo, float hi) {
    u64 r; asm("mov.b64 %0, {%1, %2};" : "=l"(r) : "f"(lo), "f"(hi)); return r;
}
__device__ __forceinline__ void upk2(u64 v, float& lo, float& hi) {
    asm("mov.b64 {%0, %1}, %2;" : "=f"(lo), "=f"(hi) : "l"(v));
}
__device__ __forceinline__ u64 add2(u64 a, u64 b) {
    u64 d; asm("add.rn.f32x2 %0, %1, %2;" : "=l"(d) : "l"(a), "l"(b)); return d;
}
__device__ __forceinline__ u64 mul2(u64 a, u64 b) {
    u64 d; asm("mul.rn.f32x2 %0, %1, %2;" : "=l"(d) : "l"(a), "l"(b)); return d;
}
__device__ __forceinline__ u64 fma2(u64 a, u64 b, u64 c) {
    u64 d; asm("fma.rn.f32x2 %0, %1, %2, %3;" : "=l"(d) : "l"(a), "l"(b), "l"(c)); return d;
}

// ---- mbarrier / bulk-copy helpers ----
__device__ __forceinline__ void mbar_init(uint32_t a, uint32_t cnt) {
    asm volatile("mbarrier.init.shared.b64 [%0], %1;" :: "r"(a), "r"(cnt) : "memory");
}
__device__ __forceinline__ void mbar_expect_tx(uint32_t a, uint32_t bytes) {
    asm volatile("mbarrier.arrive.expect_tx.shared.b64 _, [%0], %1;"
                 :: "r"(a), "r"(bytes) : "memory");
}
__device__ __forceinline__ void mbar_wait(uint32_t a, uint32_t parity) {
    asm volatile(
        "{\n\t.reg .pred P;\n\t"
        "WAIT_%=:\n\t"
        "mbarrier.try_wait.parity.acquire.cta.shared::cta.b64 P, [%0], %1, 0x989680;\n\t"
        "@P bra DONE_%=;\n\t"
        "bra WAIT_%=;\n\t"
        "DONE_%=:\n\t}"
        :: "r"(a), "r"(parity) : "memory");
}
__device__ __forceinline__ void bulk_cp(uint32_t dst, const void* src,
                                        uint32_t bytes, uint32_t mbar) {
    asm volatile(
        "cp.async.bulk.shared::cta.global.mbarrier::complete_tx::bytes "
        "[%0], [%1], %2, [%3];"
        :: "r"(dst), "l"(src), "r"(bytes), "r"(mbar) : "memory");
}

// Per-block partials: [y][b*16 + half*8 + q]; q<4: nom[kk=q], q>=4: den[kk=q-4]
__device__ float g_part[NBY * BB * 16];
__device__ unsigned int g_count = 0;   // zero-init; last block resets it

__global__ __launch_bounds__(256, 3) void clustering_fused_kernel(
    const float* __restrict__ img,      // (B,1,H,W)
    const float* __restrict__ spacing,  // (2,)
    const float* __restrict__ p,        // (B,K,H,W)
    float* __restrict__ out)
{
    extern __shared__ float sm[];                  // [NSTG][5][WW]
    __shared__ __align__(8) u64 mbar[NSTG];

    const int b    = blockIdx.z;
    const int half = blockIdx.x;
    const int h0   = blockIdx.y * CH;
    const int w0   = 4 * threadIdx.x;              // 256 threads cover W=1024
    const int idxR = (w0 + 4 < WW) ? (w0 + 4) : (WW - 1);

    const float sx = spacing[0];
    const float sy = spacing[1];
    const float smin   = fminf(sx, sy);
    const float gsmin  = GAMMA_C * smin;
    const float inv_sx = 1.0f / sx;
    const float inv_sy = 1.0f / sy;

    const u64 ISX2 = pk2(inv_sx, inv_sx);
    const u64 ISY2 = pk2(inv_sy, inv_sy);
    const u64 NEG1 = pk2(-1.0f, -1.0f);
    const u64 NEG2 = pk2(-2.0f, -2.0f);

    const float* __restrict__ Ib = img + (size_t)b * HH * WW;
    const float* __restrict__ pb = p + (size_t)b * KK * HH * WW
                                     + (size_t)half * KH * HH * WW;

    const uint32_t sm_base   = (uint32_t)__cvta_generic_to_shared(sm);
    const uint32_t mbar_base = (uint32_t)__cvta_generic_to_shared(&mbar[0]);

    // ---- init barriers, then prime the 3-stage ring with rows 0,1,2 ----
    if (threadIdx.x == 0) {
#pragma unroll
        for (int s = 0; s < NSTG; s++) mbar_init(mbar_base + 8 * s, 1);
    }
    __syncthreads();

    auto issue_set = [&](int stage, int j) {     // row-set j -> stage
        int h = h0 + j; if (h > HH - 1) h = HH - 1;
        const uint32_t mb  = mbar_base + 8 * stage;
        const uint32_t dst = sm_base + stage * SET_BYTES;
        const size_t   go  = (size_t)h * WW;
        mbar_expect_tx(mb, SET_BYTES);
        bulk_cp(dst, Ib + go, WW * 4, mb);
#pragma unroll
        for (int k = 0; k < KH; k++)
            bulk_cp(dst + (k + 1) * WW * 4, pb + (size_t)k * HH * WW + go, WW * 4, mb);
    };

    if (threadIdx.x == 0) {
        issue_set(0, 0);
        issue_set(1, 1);
        issue_set(2, 2);
    }

    u64 nom2[KH], den2[KH];
    const u64 Z = pk2(0.0f, 0.0f);
#pragma unroll
    for (int k = 0; k < KH; k++) { nom2[k] = Z; den2[k] = Z; }

#pragma unroll
    for (int r = 0; r < CH; r++) {
        const int sA = r % NSTG;            // holds row-set r   (load #(r/3))
        const int sB = (r + 1) % NSTG;      // holds row-set r+1 (load #((r+1)/3))

        mbar_wait(mbar_base + 8 * sA, (uint32_t)((r / NSTG) & 1));
        mbar_wait(mbar_base + 8 * sB, (uint32_t)(((r + 1) / NSTG) & 1));

        const float* stA = sm + sA * SETF;
        const float* stB = sm + sB * SETF;

        // ---- edge weights from I rows in smem ----
        const float4 iC = *(const float4*)(stA + w0);
        const float4 iN = *(const float4*)(stB + w0);
        const float  iR = stA[idxR];

        u64 wE01, wE23, tE01, tE23;
        {
            const u64 ic01 = pk2(iC.x, iC.y), ic23 = pk2(iC.z, iC.w);
            const u64 in01 = pk2(iN.x, iN.y), in23 = pk2(iN.z, iN.w);
            const u64 ir01 = pk2(iC.y, iC.z), ir23 = pk2(iC.w, iR);

            const u64 ix01 = fma2(ic01, NEG1, in01);
            const u64 ix23 = fma2(ic23, NEG1, in23);
            const u64 iy01 = fma2(ic01, NEG1, ir01);
            const u64 iy23 = fma2(ic23, NEG1, ir23);

            const u64 gx01 = mul2(ix01, ISX2), gx23 = mul2(ix23, ISX2);
            const u64 gy01 = mul2(iy01, ISY2), gy23 = mul2(iy23, ISY2);
            const u64 gn01 = fma2(gy01, gy01, mul2(gx01, gx01));
            const u64 gn23 = fma2(gy23, gy23, mul2(gx23, gx23));

            float g0, g1, g2, g3;
            upk2(gn01, g0, g1); upk2(gn23, g2, g3);
            const float w0_ = 1.0f / fmaf(gsmin, sqrtf(fmaxf(g0, EPS_SQRT_C)), 1.0f);
            const float w1_ = 1.0f / fmaf(gsmin, sqrtf(fmaxf(g1, EPS_SQRT_C)), 1.0f);
            const float w2_ = 1.0f / fmaf(gsmin, sqrtf(fmaxf(g2, EPS_SQRT_C)), 1.0f);
            const float w3_ = 1.0f / fmaf(gsmin, sqrtf(fmaxf(g3, EPS_SQRT_C)), 1.0f);
            wE01 = pk2(w0_, w1_); wE23 = pk2(w2_, w3_);
            tE01 = pk2(fmaf(2.0f, w0_, 1.0f), fmaf(2.0f, w1_, 1.0f));
            tE23 = pk2(fmaf(2.0f, w2_, 1.0f), fmaf(2.0f, w3_, 1.0f));
        }

#pragma unroll
        for (int k = 0; k < KH; k++) {
            const float* rowC = stA + (k + 1) * WW;
            const float* rowN = stB + (k + 1) * WW;
            const float4 c4 = *(const float4*)(rowC + w0);
            const float4 n4 = *(const float4*)(rowN + w0);
            const float  pRk = rowC[idxR];

            const u64 pc01 = pk2(c4.x, c4.y), pc23 = pk2(c4.z, c4.w);
            const u64 pr01 = pk2(c4.y, c4.z), pr23 = pk2(c4.w, pRk);
            const u64 pn01 = pk2(n4.x, n4.y), pn23 = pk2(n4.z, n4.w);

            const u64 s01 = add2(pn01, pr01), s23 = add2(pn23, pr23);
            const u64 d01 = fma2(NEG2, pc01, s01), d23 = fma2(NEG2, pc23, s23);
            const u64 t01 = fma2(wE01, d01, pc01), t23 = fma2(wE23, d23, pc23);
            nom2[k] = fma2(pc01, t01, nom2[k]);
            nom2[k] = fma2(pc23, t23, nom2[k]);
            den2[k] = fma2(pc01, tE01, den2[k]);
            den2[k] = fma2(pc23, tE23, den2[k]);
        }

        // all threads done reading stage sA -> refill it with row-set r+3
        __syncthreads();
        if (r + 3 <= CH) {
            if (threadIdx.x == 0) issue_set(sA, r + 3);
        }
    }

    // ---- horizontal add of packed accumulators ----
    float nom[KH], den[KH];
#pragma unroll
    for (int k = 0; k < KH; k++) {
        float a, b2;
        upk2(nom2[k], a, b2); nom[k] = a + b2;
        upk2(den2[k], a, b2); den[k] = a + b2;
    }

    // ---- Block reduction of the 8 quantities ----
    __shared__ float sred[8][8];
    const int lane = threadIdx.x & 31;
    const int warp = threadIdx.x >> 5;

#pragma unroll
    for (int q = 0; q < 8; q++) {
        float v = (q < 4) ? nom[q] : den[q - 4];
#pragma unroll
        for (int off = 16; off > 0; off >>= 1)
            v += __shfl_xor_sync(0xFFFFFFFFu, v, off);
        if (lane == 0) sred[warp][q] = v;
    }
    __syncthreads();

    if (threadIdx.x < 8) {
        const int q = threadIdx.x;
        float v = 0.0f;
#pragma unroll
        for (int wp = 0; wp < 8; wp++) v += sred[wp][q];
        g_part[(size_t)blockIdx.y * (BB * 16) + b * 16 + half * 8 + q] = v;
    }

    // ---- Last-block finalize (ticket pattern; counter self-resets) ----
    __shared__ bool s_last;
    __threadfence();
    __syncthreads();
    if (threadIdx.x == 0) {
        unsigned int ticket = atomicAdd(&g_count, 1u);
        s_last = (ticket == NBLOCKS - 1);
    }
    __syncthreads();

    if (s_last) {
        __shared__ float s[256];
        __shared__ float c[BB * KK];
        const int t = threadIdx.x;
        const int q  = t & 127;
        const int hy = t >> 7;

        float v = 0.0f;
#pragma unroll 8
        for (int y = hy * (NBY / 2); y < (hy + 1) * (NBY / 2); y++)
            v += g_part[(size_t)y * (BB * 16) + q];
        s[t] = v;
        __syncthreads();

        if (t < BB * KK) {
            const int bb = t >> 3, k = t & 7;
            const int hf = k >> 2, kk = k & 3;
            const int cn = bb * 16 + hf * 8 + kk;
            const int cd = cn + 4;
            const float tn = s[cn] + s[128 + cn];
            const float td = s[cd] + s[128 + cd];
            c[t] = tn / td;                // cut_cost[b,k]
        }
        __syncthreads();

        if (t == 0) {
            float sum = 0.0f;
            for (int j = 0; j < BB * KK; j++) sum += c[j];
            out[0] = (float)(BB * KK) - sum;
            g_count = 0;                   // reset for next graph replay
        }
    }
}

extern "C" void kernel_launch(void* const* d_in, const int* in_sizes, int n_in,
                              void* d_out, int out_size) {
    const float* img     = (const float*)d_in[0];  // (8,1,1024,1024)
    const float* spacing = (const float*)d_in[1];  // (2,)
    const float* p       = (const float*)d_in[2];  // (8,8,1024,1024)
    float* out = (float*)d_out;

    cudaFuncSetAttribute(clustering_fused_kernel,
                         cudaFuncAttributeMaxDynamicSharedMemorySize, DYN_SMEM);

    dim3 grid(2, NBY, BB);   // (2, 128, 8) = 2048 blocks
    clustering_fused_kernel<<<grid, 256, DYN_SMEM>>>(img, spacing, p, out);
}